// round 13
// baseline (speedup 1.0000x reference)
#include <cuda_runtime.h>
#include <float.h>

#define N_  2
#define C_  256
#define H_  56
#define W_  56
#define R_  512
#define P_  7
#define SCALE_ 0.0625f
#define PLANE_ (H_ * W_)      // 3136

// NHWC tensors: [b][hw][c]
__device__ float g_t[(size_t)N_ * PLANE_ * C_];   // features
__device__ float g_h[(size_t)N_ * PLANE_ * C_];   // horiz pairmax
__device__ float g_v[(size_t)N_ * PLANE_ * C_];   // vert  pairmax
__device__ float g_2[(size_t)N_ * PLANE_ * C_];   // 2x2   pairmax

__device__ __forceinline__ float4 fmax4(float4 a, float4 b) {
    return make_float4(fmaxf(a.x,b.x), fmaxf(a.y,b.y), fmaxf(a.z,b.z), fmaxf(a.w,b.w));
}

// ---------- kernel 1: fused NCHW->NHWC transpose + pairmax pyramids ----------
// block = (row h, 32-channel group, image b); reads rows h and h+1 (clamped)
__global__ __launch_bounds__(256) void prep_kernel(const float* __restrict__ f)
{
    __shared__ float s[32 * 113];   // [c][j], j<112: row h then row hd; stride 113 (17 mod 32, coprime)
    const int h  = blockIdx.x;
    const int c0 = blockIdx.y * 32;
    const int b  = blockIdx.z;
    const int hd = min(h + 1, H_ - 1);
    const int t  = threadIdx.x;

    // coalesced NCHW loads: contiguous w per (c,row)
    for (int i = t; i < 32 * 112; i += 256) {
        int c = i / 112, j = i - c * 112;
        int row = (j < W_) ? h : hd;
        int w   = (j < W_) ? j : j - W_;
        s[c * 113 + j] = __ldg(f + ((size_t)b * C_ + c0 + c) * PLANE_ + row * W_ + w);
    }
    __syncthreads();

    // compute + transposed coalesced writes (c fast across threads)
    for (int i = t; i < 32 * W_; i += 256) {
        int c = i & 31;
        int w = i >> 5;
        int wr = min(w + 1, W_ - 1);
        float a  = s[c * 113 + w];
        float r  = s[c * 113 + wr];
        float d  = s[c * 113 + W_ + w];
        float dr = s[c * 113 + W_ + wr];
        float mh = fmaxf(a, r);
        float mv = fmaxf(a, d);
        float m2 = fmaxf(mh, fmaxf(d, dr));
        size_t o = ((size_t)b * PLANE_ + h * W_ + w) * C_ + c0 + c;
        g_t[o] = a;  g_h[o] = mh;  g_v[o] = mv;  g_2[o] = m2;
    }
}

// ---------- kernel 2: pooling; 512 thr, warp-unit = (bin, 128 ch), flat 9-load batch ----------
__global__ __launch_bounds__(512) void roipool_kernel(
    const float* __restrict__ rois,
    float* __restrict__ out)
{
    __shared__ int   sdesc[P_ * P_];
    __shared__ int   sb;
    __shared__ __align__(16) float stage[128 * P_ * P_];

    const int t    = threadIdx.x;
    const int lane = t & 31;
    const int wrp  = t >> 5;                   // 16 warps
    const int r    = blockIdx.x >> 1;
    const int c0   = (blockIdx.x & 1) * 128;

    if (t < P_ * P_) {
        const float* roi = rois + r * 5;
        int x1 = __float2int_rn(roi[1] * SCALE_);   // half-even == jnp.round
        int y1 = __float2int_rn(roi[2] * SCALE_);
        int x2 = __float2int_rn(roi[3] * SCALE_);
        int y2 = __float2int_rn(roi[4] * SCALE_);
        float bin_h = (float)max(y2 - y1 + 1, 1) * (1.0f / P_);
        float bin_w = (float)max(x2 - x1 + 1, 1) * (1.0f / P_);

        int ph = t / P_, pw = t - ph * P_;
        int hs = min(max((int)floorf((float)ph       * bin_h) + y1, 0), H_);
        int he = min(max((int)ceilf ((float)(ph + 1) * bin_h) + y1, 0), H_);
        int ws = min(max((int)floorf((float)pw       * bin_w) + x1, 0), W_);
        int we = min(max((int)ceilf ((float)(pw + 1) * bin_w) + x1, 0), W_);

        int dh = max(he - hs, 0);
        int dw = max(we - ws, 0);
        sdesc[t] = (hs * W_ + ws) | (dh << 16) | (dw << 22);
        if (t == 0) sb = (int)roi[0];               // trunc == astype(int32)
    }
    __syncthreads();

    const int b = sb;
    for (int u = wrp; u < P_ * P_; u += 16) {       // <= 4 sequential units/warp
        int d    = sdesc[u];
        int base =  d        & 0xFFFF;
        int dh   = (d >> 16) & 0x3F;
        int dw   =  d >> 22;
        int ph2 = dh >> 1, th = dh & 1;
        int pw2 = dw >> 1, tw = dw & 1;

        size_t o = ((size_t)b * PLANE_ + base) * C_ + c0 + 4 * lane;   // floats

        float4 m = make_float4(-FLT_MAX, -FLT_MAX, -FLT_MAX, -FLT_MAX);

        // window = 2x2 quads (g_2) + odd row (g_h) + odd col (g_v) + corner (g_t)
        #pragma unroll
        for (int i = 0; i < 2; ++i)
            #pragma unroll
            for (int j = 0; j < 2; ++j)
                if (i < ph2 && j < pw2)
                    m = fmax4(m, __ldg((const float4*)(g_2 + o + (size_t)(2*i*W_ + 2*j) * C_)));
        #pragma unroll
        for (int j = 0; j < 2; ++j)
            if (th && j < pw2)
                m = fmax4(m, __ldg((const float4*)(g_h + o + (size_t)((dh-1)*W_ + 2*j) * C_)));
        #pragma unroll
        for (int i = 0; i < 2; ++i)
            if (tw && i < ph2)
                m = fmax4(m, __ldg((const float4*)(g_v + o + (size_t)(2*i*W_ + dw-1) * C_)));
        if (th && tw)
            m = fmax4(m, __ldg((const float4*)(g_t + o + (size_t)((dh-1)*W_ + dw-1) * C_)));

        if (dh == 0 || dw == 0) m = make_float4(0.f, 0.f, 0.f, 0.f);

        stage[(4 * lane + 0) * (P_ * P_) + u] = m.x;
        stage[(4 * lane + 1) * (P_ * P_) + u] = m.y;
        stage[(4 * lane + 2) * (P_ * P_) + u] = m.z;
        stage[(4 * lane + 3) * (P_ * P_) + u] = m.w;
    }
    __syncthreads();

    const size_t obase = ((size_t)r * C_ + c0) * (P_ * P_);
    const float4* s4 = (const float4*)stage;
    float4* o4 = (float4*)(out + obase);
    #pragma unroll
    for (int k = 0; k < (128 * P_ * P_ / 4 + 511) / 512; ++k) {
        int i = t + k * 512;
        if (i < 128 * P_ * P_ / 4) o4[i] = s4[i];
    }
}

extern "C" void kernel_launch(void* const* d_in, const int* in_sizes, int n_in,
                              void* d_out, int out_size)
{
    const float* features = (const float*)d_in[0];
    const float* rois     = (const float*)d_in[1];
    float* out            = (float*)d_out;

    dim3 pg(H_, C_ / 32, N_);                 // 56 x 8 x 2 = 896 blocks
    prep_kernel<<<pg, 256>>>(features);

    roipool_kernel<<<R_ * 2, 512>>>(rois, out);   // 1024 blocks
}